// round 3
// baseline (speedup 1.0000x reference)
#include <cuda_runtime.h>
#include <cuda_bf16.h>
#include <math.h>

// Problem shape (fixed)
#define BATCH 8
#define LQ    2048
#define LK    2048
#define DQ    1024
#define DKEY  1024
#define DV    1024

// Scratch: Q projection [B,LQ,DKEY] (64MB) and scores/attn [B,LQ,LK] (128MB)
__device__ float g_Q[(size_t)BATCH * LQ * DKEY];
__device__ float g_S[(size_t)BATCH * LQ * LK];

// ---------------------------------------------------------------------------
// Tiled SGEMM: C[M,N] = alpha * A[M,K] * op(B)
//   TRANSB == false: B is row-major [K,N]
//   TRANSB == true : B is row-major [N,K]  (C = alpha * A * B^T)
// Block tile 128x128, K-tile 16, 256 threads, 8x8 per-thread microtile.
// M % 128 == 0, N % 128 == 0, K % 16 == 0 (true for all three calls).
// ---------------------------------------------------------------------------
template <bool TRANSB>
__global__ __launch_bounds__(256, 2)
void sgemm128(const float* __restrict__ A,
              const float* __restrict__ B,
              float* __restrict__ C,
              int M, int N, int K,
              size_t strideA, size_t strideB, size_t strideC,
              float alpha)
{
    constexpr int BM = 128, BN = 128, BK = 16;
    __shared__ float As[BK][BM + 4];
    __shared__ float Bs[BK][BN + 4];

    const int tid = threadIdx.x;
    const int bz  = blockIdx.z;
    const int blockRow = blockIdx.y * BM;
    const int blockCol = blockIdx.x * BN;

    const float* Ab = A + (size_t)bz * strideA + (size_t)blockRow * K;
    const float* Bb;
    if (TRANSB) Bb = B + (size_t)bz * strideB + (size_t)blockCol * K;
    else        Bb = B + (size_t)bz * strideB + blockCol;

    const int ty = tid >> 4;          // 0..15
    const int tx = tid & 15;          // 0..15
    const int rowBase = ty * 8;
    const int colBase = tx * 8;

    float acc[8][8];
    #pragma unroll
    for (int i = 0; i < 8; i++)
        #pragma unroll
        for (int j = 0; j < 8; j++) acc[i][j] = 0.0f;

    // A-loader indices (transpose into As[k][m]): read float4 along K
    const int a_m0 = tid >> 2;          // 0..63
    const int a_k4 = (tid & 3) * 4;     // 0,4,8,12

    // B-loader indices
    const int bn_k0 = tid >> 5;         // 0..7  (row-major B)
    const int bn_n4 = (tid & 31) * 4;   // 0..124
    const int bt_n0 = tid >> 2;         // 0..63 (transposed B)
    const int bt_k4 = (tid & 3) * 4;

    const int numKT = K / BK;
    for (int kt = 0; kt < numKT; kt++) {
        const int k0 = kt * BK;

        // Load A tile (128 x 16) transposed
        #pragma unroll
        for (int i = 0; i < 2; i++) {
            int m = a_m0 + i * 64;
            float4 v = *(const float4*)(Ab + (size_t)m * K + k0 + a_k4);
            As[a_k4 + 0][m] = v.x;
            As[a_k4 + 1][m] = v.y;
            As[a_k4 + 2][m] = v.z;
            As[a_k4 + 3][m] = v.w;
        }

        // Load B tile
        if (TRANSB) {
            #pragma unroll
            for (int i = 0; i < 2; i++) {
                int n = bt_n0 + i * 64;
                float4 v = *(const float4*)(Bb + (size_t)n * K + k0 + bt_k4);
                Bs[bt_k4 + 0][n] = v.x;
                Bs[bt_k4 + 1][n] = v.y;
                Bs[bt_k4 + 2][n] = v.z;
                Bs[bt_k4 + 3][n] = v.w;
            }
        } else {
            #pragma unroll
            for (int i = 0; i < 2; i++) {
                int k = bn_k0 + i * 8;
                float4 v = *(const float4*)(Bb + (size_t)(k0 + k) * N + bn_n4);
                *(float4*)&Bs[k][bn_n4] = v;
            }
        }

        __syncthreads();

        #pragma unroll
        for (int k = 0; k < BK; k++) {
            float a[8], b[8];
            const float4* ap = (const float4*)&As[k][rowBase];
            const float4* bp = (const float4*)&Bs[k][colBase];
            float4 a0 = ap[0], a1 = ap[1];
            float4 b0 = bp[0], b1 = bp[1];
            a[0]=a0.x; a[1]=a0.y; a[2]=a0.z; a[3]=a0.w;
            a[4]=a1.x; a[5]=a1.y; a[6]=a1.z; a[7]=a1.w;
            b[0]=b0.x; b[1]=b0.y; b[2]=b0.z; b[3]=b0.w;
            b[4]=b1.x; b[5]=b1.y; b[6]=b1.z; b[7]=b1.w;
            #pragma unroll
            for (int i = 0; i < 8; i++)
                #pragma unroll
                for (int j = 0; j < 8; j++)
                    acc[i][j] = fmaf(a[i], b[j], acc[i][j]);
        }

        __syncthreads();
    }

    // Epilogue
    float* Cb = C + (size_t)bz * strideC;
    #pragma unroll
    for (int i = 0; i < 8; i++) {
        float* crow = Cb + (size_t)(blockRow + rowBase + i) * N + blockCol + colBase;
        float4 v0, v1;
        v0.x = alpha * acc[i][0]; v0.y = alpha * acc[i][1];
        v0.z = alpha * acc[i][2]; v0.w = alpha * acc[i][3];
        v1.x = alpha * acc[i][4]; v1.y = alpha * acc[i][5];
        v1.z = alpha * acc[i][6]; v1.w = alpha * acc[i][7];
        *(float4*)(crow + 0) = v0;
        *(float4*)(crow + 4) = v1;
    }
}

// ---------------------------------------------------------------------------
// Masked softmax over rows of S (in place). One block per (b, q) row.
// Positions s >= valid_lens[b] are filled with -1e6 before softmax,
// matching d2l masked_softmax.
// ---------------------------------------------------------------------------
__global__ __launch_bounds__(256)
void softmax_rows(float* __restrict__ S, const int* __restrict__ valid_lens)
{
    const int row = blockIdx.x;
    const int b   = row >> 11;            // / LQ (LQ == 2048)
    const int valid = valid_lens[b];
    float* rowp = S + (size_t)row * LK;

    const int tid  = threadIdx.x;
    const int lane = tid & 31;
    const int warp = tid >> 5;
    __shared__ float sred[8];

    float x[8];
    float mx = -3.0e38f;
    #pragma unroll
    for (int i = 0; i < 8; i++) {
        int s = tid + i * 256;
        float v = rowp[s];
        if (s >= valid) v = -1.0e6f;
        x[i] = v;
        mx = fmaxf(mx, v);
    }
    #pragma unroll
    for (int off = 16; off > 0; off >>= 1)
        mx = fmaxf(mx, __shfl_xor_sync(0xffffffffu, mx, off));
    if (lane == 0) sred[warp] = mx;
    __syncthreads();
    if (warp == 0) {
        float v = (lane < 8) ? sred[lane] : -3.0e38f;
        #pragma unroll
        for (int off = 4; off > 0; off >>= 1)
            v = fmaxf(v, __shfl_xor_sync(0xffffffffu, v, off));
        if (lane == 0) sred[0] = v;
    }
    __syncthreads();
    mx = sred[0];
    __syncthreads();

    float sum = 0.0f;
    #pragma unroll
    for (int i = 0; i < 8; i++) {
        float e = __expf(x[i] - mx);
        x[i] = e;
        sum += e;
    }
    #pragma unroll
    for (int off = 16; off > 0; off >>= 1)
        sum += __shfl_xor_sync(0xffffffffu, sum, off);
    if (lane == 0) sred[warp] = sum;
    __syncthreads();
    if (warp == 0) {
        float v = (lane < 8) ? sred[lane] : 0.0f;
        #pragma unroll
        for (int off = 4; off > 0; off >>= 1)
            v += __shfl_xor_sync(0xffffffffu, v, off);
        if (lane == 0) sred[0] = v;
    }
    __syncthreads();
    const float inv = 1.0f / sred[0];

    #pragma unroll
    for (int i = 0; i < 8; i++)
        rowp[tid + i * 256] = x[i] * inv;
}

// ---------------------------------------------------------------------------
extern "C" void kernel_launch(void* const* d_in, const int* in_sizes, int n_in,
                              void* d_out, int out_size)
{
    const float* queries = (const float*)d_in[0];  // [B, LQ, DQ]
    const float* keys    = (const float*)d_in[1];  // [B, LK, DKEY]
    const float* values  = (const float*)d_in[2];  // [B, LK, DV]
    const int*   vlens   = (const int*)  d_in[3];  // [B]
    const float* W_q     = (const float*)d_in[4];  // [DQ, DKEY]
    float*       out     = (float*)d_out;          // [B, LQ, DV]

    float* qbuf = nullptr;
    float* sbuf = nullptr;
    cudaGetSymbolAddress((void**)&qbuf, g_Q);
    cudaGetSymbolAddress((void**)&sbuf, g_S);

    dim3 blk(256);

    // 1) Q = queries @ W_q   — flatten batch: [B*LQ, DQ] @ [DQ, DKEY]
    {
        dim3 grid(DKEY / 128, (BATCH * LQ) / 128, 1);
        sgemm128<false><<<grid, blk>>>(queries, W_q, qbuf,
                                       BATCH * LQ, DKEY, DQ,
                                       0, 0, 0, 1.0f);
    }

    // 2) S = Q @ K^T / sqrt(DKEY)  — batched
    {
        dim3 grid(LK / 128, LQ / 128, BATCH);
        sgemm128<true><<<grid, blk>>>(qbuf, keys, sbuf,
                                      LQ, LK, DKEY,
                                      (size_t)LQ * DKEY,
                                      (size_t)LK * DKEY,
                                      (size_t)LQ * LK,
                                      0.03125f /* 1/sqrt(1024) */);
    }

    // 3) masked softmax (in place on S)
    softmax_rows<<<BATCH * LQ, blk>>>(sbuf, vlens);

    // 4) out = A @ V — batched
    {
        dim3 grid(DV / 128, LQ / 128, BATCH);
        sgemm128<false><<<grid, blk>>>(sbuf, values, out,
                                       LQ, DV, LK,
                                       (size_t)LQ * LK,
                                       (size_t)LK * DV,
                                       (size_t)LQ * DV,
                                       1.0f);
    }
}

// round 17
// speedup vs baseline: 2.1063x; 2.1063x over previous
#include <cuda_runtime.h>
#include <cuda_bf16.h>
#include <cstdint>
#include <math.h>

// Problem shape (fixed)
#define BATCH 8
#define LQ    2048
#define LK    2048
#define DQ    1024
#define DKEY  1024
#define DV    1024

// ---------------------------------------------------------------------------
// Scratch (device globals; no allocation allowed)
// ---------------------------------------------------------------------------
__device__ __nv_bfloat16 g_qh[(size_t)BATCH * LQ * DQ];     // queries split
__device__ __nv_bfloat16 g_ql[(size_t)BATCH * LQ * DQ];
__device__ __nv_bfloat16 g_wth[(size_t)DKEY * DQ];          // W_q^T split
__device__ __nv_bfloat16 g_wtl[(size_t)DKEY * DQ];
__device__ __nv_bfloat16 g_Qh[(size_t)BATCH * LQ * DKEY];   // projected Q split
__device__ __nv_bfloat16 g_Ql[(size_t)BATCH * LQ * DKEY];
__device__ __nv_bfloat16 g_kh[(size_t)BATCH * LK * DKEY];   // keys split
__device__ __nv_bfloat16 g_kl[(size_t)BATCH * LK * DKEY];
__device__ float         g_S [(size_t)BATCH * LQ * LK];     // scores fp32
__device__ __nv_bfloat16 g_Ah[(size_t)BATCH * LQ * LK];     // attn split
__device__ __nv_bfloat16 g_Al[(size_t)BATCH * LQ * LK];
__device__ __nv_bfloat16 g_vth[(size_t)BATCH * DV * LK];    // V^T split
__device__ __nv_bfloat16 g_vtl[(size_t)BATCH * DV * LK];

// ---------------------------------------------------------------------------
// mma.sync helpers (sm_80-baseline PTX — legal on compute_103)
// ---------------------------------------------------------------------------
__device__ __forceinline__ uint32_t smem_to_u32(const void* smem_ptr) {
    uint32_t addr;
    asm("{ .reg .u64 tmp; cvta.to.shared.u64 tmp, %1; cvt.u32.u64 %0, tmp; }"
        : "=r"(addr) : "l"(smem_ptr));
    return addr;
}

#define LDMATRIX_X4(r0, r1, r2, r3, addr) \
    asm volatile("ldmatrix.sync.aligned.m8n8.x4.shared.b16 {%0, %1, %2, %3}, [%4];" \
        : "=r"(r0), "=r"(r1), "=r"(r2), "=r"(r3) : "r"(addr))

#define LDMATRIX_X2(r0, r1, addr) \
    asm volatile("ldmatrix.sync.aligned.m8n8.x2.shared.b16 {%0, %1}, [%2];" \
        : "=r"(r0), "=r"(r1) : "r"(addr))

#define MMA_BF16(d, a, b) \
    asm volatile("mma.sync.aligned.m16n8k16.row.col.f32.bf16.bf16.f32 " \
        "{%0, %1, %2, %3}, {%4, %5, %6, %7}, {%8, %9}, {%0, %1, %2, %3};" \
        : "+f"((d)[0]), "+f"((d)[1]), "+f"((d)[2]), "+f"((d)[3]) \
        : "r"((a)[0]), "r"((a)[1]), "r"((a)[2]), "r"((a)[3]), \
          "r"((b)[0]), "r"((b)[1]))

// ---------------------------------------------------------------------------
// HMMA GEMM: C[M,N] = alpha * (Ah+Al)[M,K] @ (Bh+Bl)[N,K]^T  (3-term bf16x3)
// 128x128 per CTA, 8 warps (2x4), warp tile 64x32, K-chunk 32.
// Smem tiles padded to 80B row stride (conflict-free ldmatrix).
// EPI=0: fp32 C.  EPI=1: split bf16 (Ch, Cl).
// ---------------------------------------------------------------------------
#define TILE_STRIDE 80              // bytes per padded 32-bf16 row
#define TILE_BYTES  (128 * TILE_STRIDE)

template <int EPI>
__global__ __launch_bounds__(256)
void hmma_gemm(const __nv_bfloat16* __restrict__ Ah, const __nv_bfloat16* __restrict__ Al,
               const __nv_bfloat16* __restrict__ Bh, const __nv_bfloat16* __restrict__ Bl,
               float* __restrict__ Cf,
               __nv_bfloat16* __restrict__ Ch, __nv_bfloat16* __restrict__ Cl,
               int N, int K,
               size_t sA, size_t sB, size_t sC, float alpha)
{
    __shared__ __align__(16) uint8_t sm[4 * TILE_BYTES];   // 40 KB static
    uint8_t* const smAh = sm;
    uint8_t* const smAl = sm + TILE_BYTES;
    uint8_t* const smBh = sm + 2 * TILE_BYTES;
    uint8_t* const smBl = sm + 3 * TILE_BYTES;
    const uint32_t suAh = smem_to_u32(smAh);
    const uint32_t suAl = smem_to_u32(smAl);
    const uint32_t suBh = smem_to_u32(smBh);
    const uint32_t suBl = smem_to_u32(smBl);

    const int tid  = threadIdx.x;
    const int wid  = tid >> 5;
    const int lane = tid & 31;
    const int wm   = wid & 1;        // 0..1  (64-row group)
    const int wn   = wid >> 1;       // 0..3  (32-col group)

    const int rowBlk = blockIdx.y * 128;
    const int colBlk = blockIdx.x * 128;
    const int bz = blockIdx.z;

    const __nv_bfloat16* Ahb = Ah + (size_t)bz * sA + (size_t)rowBlk * K;
    const __nv_bfloat16* Alb = Al + (size_t)bz * sA + (size_t)rowBlk * K;
    const __nv_bfloat16* Bhb = Bh + (size_t)bz * sB + (size_t)colBlk * K;
    const __nv_bfloat16* Blb = Bl + (size_t)bz * sB + (size_t)colBlk * K;

    float acc[4][4][4];
    #pragma unroll
    for (int i = 0; i < 4; i++)
        #pragma unroll
        for (int j = 0; j < 4; j++)
            #pragma unroll
            for (int v = 0; v < 4; v++) acc[i][j][v] = 0.0f;

    // ldmatrix lane addressing (precomputed pieces)
    const int aRow  = lane & 15;                 // + m-tile row base
    const int aColB = (lane >> 4) << 4;          // 0 or 16 bytes
    const int bRow  = lane & 7;                  // + n-tile row base
    const int bColB = ((lane >> 3) & 1) << 4;    // 0 or 16 bytes

    const int numChunks = K >> 5;                // K-chunk = 32
    for (int kt = 0; kt < numChunks; kt++) {
        const int k0 = kt << 5;

        // Load 4 tiles: 128 rows x 32 bf16 (= 4 x 16B per row)
        #pragma unroll
        for (int i = 0; i < 2; i++) {
            const int idx = tid + i * 256;       // 0..511
            const int r = idx >> 2;
            const int c = idx & 3;
            const size_t goff = (size_t)r * K + k0 + c * 8;
            const int so = r * TILE_STRIDE + c * 16;
            *(uint4*)(smAh + so) = *(const uint4*)(Ahb + goff);
            *(uint4*)(smAl + so) = *(const uint4*)(Alb + goff);
            *(uint4*)(smBh + so) = *(const uint4*)(Bhb + goff);
            *(uint4*)(smBl + so) = *(const uint4*)(Blb + goff);
        }
        __syncthreads();

        #pragma unroll
        for (int kk = 0; kk < 2; kk++) {
            const int kb = kk * 32;              // byte offset of k-step in row

            // A fragments (hi and lo) for 4 m-tiles
            uint32_t fah[4][4], fal[4][4];
            #pragma unroll
            for (int mi = 0; mi < 4; mi++) {
                const int row = wm * 64 + mi * 16 + aRow;
                const uint32_t off = (uint32_t)(row * TILE_STRIDE + kb + aColB);
                LDMATRIX_X4(fah[mi][0], fah[mi][1], fah[mi][2], fah[mi][3], suAh + off);
                LDMATRIX_X4(fal[mi][0], fal[mi][1], fal[mi][2], fal[mi][3], suAl + off);
            }
            // B fragments (hi and lo) for 4 n-tiles
            uint32_t fbh[4][2], fbl[4][2];
            #pragma unroll
            for (int ni = 0; ni < 4; ni++) {
                const int row = wn * 32 + ni * 8 + bRow;
                const uint32_t off = (uint32_t)(row * TILE_STRIDE + kb + bColB);
                LDMATRIX_X2(fbh[ni][0], fbh[ni][1], suBh + off);
                LDMATRIX_X2(fbl[ni][0], fbl[ni][1], suBl + off);
            }
            // 3-term MMA
            #pragma unroll
            for (int mi = 0; mi < 4; mi++)
                #pragma unroll
                for (int ni = 0; ni < 4; ni++) {
                    MMA_BF16(acc[mi][ni], fah[mi], fbh[ni]);
                    MMA_BF16(acc[mi][ni], fah[mi], fbl[ni]);
                    MMA_BF16(acc[mi][ni], fal[mi], fbh[ni]);
                }
        }
        __syncthreads();
    }

    // Epilogue
    const int g  = lane >> 2;
    const int qp = lane & 3;
    #pragma unroll
    for (int mi = 0; mi < 4; mi++) {
        #pragma unroll
        for (int ni = 0; ni < 4; ni++) {
            const int m0 = rowBlk + wm * 64 + mi * 16 + g;
            const int n0 = colBlk + wn * 32 + ni * 8 + 2 * qp;
            const float* a = acc[mi][ni];
            if (EPI == 0) {
                float2 v0; v0.x = alpha * a[0]; v0.y = alpha * a[1];
                float2 v1; v1.x = alpha * a[2]; v1.y = alpha * a[3];
                *(float2*)(Cf + (size_t)bz * sC + (size_t)m0 * N + n0) = v0;
                *(float2*)(Cf + (size_t)bz * sC + (size_t)(m0 + 8) * N + n0) = v1;
            } else {
                #pragma unroll
                for (int hrow = 0; hrow < 2; hrow++) {
                    const float v0 = alpha * a[hrow * 2 + 0];
                    const float v1 = alpha * a[hrow * 2 + 1];
                    const __nv_bfloat16 h0 = __float2bfloat16(v0);
                    const __nv_bfloat16 h1 = __float2bfloat16(v1);
                    const __nv_bfloat16 l0 = __float2bfloat16(v0 - __bfloat162float(h0));
                    const __nv_bfloat16 l1 = __float2bfloat16(v1 - __bfloat162float(h1));
                    __nv_bfloat162 hp; hp.x = h0; hp.y = h1;
                    __nv_bfloat162 lp; lp.x = l0; lp.y = l1;
                    const size_t o = (size_t)bz * sC + (size_t)(m0 + hrow * 8) * N + n0;
                    *(__nv_bfloat162*)(Ch + o) = hp;
                    *(__nv_bfloat162*)(Cl + o) = lp;
                }
            }
        }
    }
}

// ---------------------------------------------------------------------------
// fp32 -> (hi, lo) bf16 split, elementwise (n % 4 == 0)
// ---------------------------------------------------------------------------
__global__ __launch_bounds__(256)
void convert_split(const float* __restrict__ in,
                   __nv_bfloat16* __restrict__ oh, __nv_bfloat16* __restrict__ ol,
                   size_t n4)
{
    size_t i = ((size_t)blockIdx.x * 256 + threadIdx.x);
    if (i >= n4) return;
    i *= 4;
    float4 v = *(const float4*)(in + i);
    float vv[4] = {v.x, v.y, v.z, v.w};
    __nv_bfloat16 h[4], l[4];
    #pragma unroll
    for (int j = 0; j < 4; j++) {
        h[j] = __float2bfloat16(vv[j]);
        l[j] = __float2bfloat16(vv[j] - __bfloat162float(h[j]));
    }
    __nv_bfloat162 hp0; hp0.x = h[0]; hp0.y = h[1];
    __nv_bfloat162 hp1; hp1.x = h[2]; hp1.y = h[3];
    __nv_bfloat162 lp0; lp0.x = l[0]; lp0.y = l[1];
    __nv_bfloat162 lp1; lp1.x = l[2]; lp1.y = l[3];
    *(__nv_bfloat162*)(oh + i) = hp0;
    *(__nv_bfloat162*)(oh + i + 2) = hp1;
    *(__nv_bfloat162*)(ol + i) = lp0;
    *(__nv_bfloat162*)(ol + i + 2) = lp1;
}

// ---------------------------------------------------------------------------
// Transpose + split: in [R, C] fp32 (row-major) -> out [C, R] bf16 hi/lo.
// ---------------------------------------------------------------------------
__global__ __launch_bounds__(256)
void transpose_split(const float* __restrict__ in,
                     __nv_bfloat16* __restrict__ oh, __nv_bfloat16* __restrict__ ol,
                     int R, int C, size_t inStride, size_t outStride)
{
    __shared__ float t[32][33];
    const int bx = blockIdx.x * 32;
    const int by = blockIdx.y * 32;
    const int tx = threadIdx.x, ty = threadIdx.y;
    const float* ib = in + (size_t)blockIdx.z * inStride;

    #pragma unroll
    for (int i = 0; i < 4; i++)
        t[ty + i * 8][tx] = ib[(size_t)(by + ty + i * 8) * C + bx + tx];
    __syncthreads();

    #pragma unroll
    for (int i = 0; i < 4; i++) {
        const int orow = bx + ty + i * 8;
        const int ocol = by + tx;
        const float v = t[tx][ty + i * 8];
        __nv_bfloat16 h = __float2bfloat16(v);
        __nv_bfloat16 l = __float2bfloat16(v - __bfloat162float(h));
        const size_t o = (size_t)blockIdx.z * outStride + (size_t)orow * R + ocol;
        oh[o] = h;
        ol[o] = l;
    }
}

// ---------------------------------------------------------------------------
// Masked softmax over rows of S; writes split bf16 attention weights.
// ---------------------------------------------------------------------------
__global__ __launch_bounds__(256)
void softmax_rows_split(const float* __restrict__ S, const int* __restrict__ valid_lens,
                        __nv_bfloat16* __restrict__ Ah, __nv_bfloat16* __restrict__ Al)
{
    const int row = blockIdx.x;
    const int b   = row >> 11;
    const int valid = valid_lens[b];
    const float* rowp = S + (size_t)row * LK;

    const int tid  = threadIdx.x;
    const int lane = tid & 31;
    const int warp = tid >> 5;
    __shared__ float sred[8];

    float x[8];
    float mx = -3.0e38f;
    #pragma unroll
    for (int i = 0; i < 8; i++) {
        int s = tid + i * 256;
        float v = rowp[s];
        if (s >= valid) v = -1.0e6f;
        x[i] = v;
        mx = fmaxf(mx, v);
    }
    #pragma unroll
    for (int off = 16; off > 0; off >>= 1)
        mx = fmaxf(mx, __shfl_xor_sync(0xffffffffu, mx, off));
    if (lane == 0) sred[warp] = mx;
    __syncthreads();
    if (warp == 0) {
        float v = (lane < 8) ? sred[lane] : -3.0e38f;
        #pragma unroll
        for (int off = 4; off > 0; off >>= 1)
            v = fmaxf(v, __shfl_xor_sync(0xffffffffu, v, off));
        if (lane == 0) sred[0] = v;
    }
    __syncthreads();
    mx = sred[0];
    __syncthreads();

    float sum = 0.0f;
    #pragma unroll
    for (int i = 0; i < 8; i++) {
        float e = __expf(x[i] - mx);
        x[i] = e;
        sum += e;
    }
    #pragma unroll
    for (int off = 16; off > 0; off >>= 1)
        sum += __shfl_xor_sync(0xffffffffu, sum, off);
    if (lane == 0) sred[warp] = sum;
    __syncthreads();
    if (warp == 0) {
        float v = (lane < 8) ? sred[lane] : 0.0f;
        #pragma unroll
        for (int off = 4; off > 0; off >>= 1)
            v += __shfl_xor_sync(0xffffffffu, v, off);
        if (lane == 0) sred[0] = v;
    }
    __syncthreads();
    const float inv = 1.0f / sred[0];

    #pragma unroll
    for (int i = 0; i < 8; i++) {
        const float v = x[i] * inv;
        const __nv_bfloat16 h = __float2bfloat16(v);
        const __nv_bfloat16 l = __float2bfloat16(v - __bfloat162float(h));
        const size_t o = (size_t)row * LK + tid + i * 256;
        Ah[o] = h;
        Al[o] = l;
    }
}

// ---------------------------------------------------------------------------
extern "C" void kernel_launch(void* const* d_in, const int* in_sizes, int n_in,
                              void* d_out, int out_size)
{
    const float* queries = (const float*)d_in[0];  // [B, LQ, DQ]
    const float* keys    = (const float*)d_in[1];  // [B, LK, DKEY]
    const float* values  = (const float*)d_in[2];  // [B, LK, DV]
    const int*   vlens   = (const int*)  d_in[3];  // [B]
    const float* W_q     = (const float*)d_in[4];  // [DQ, DKEY]
    float*       out     = (float*)d_out;          // [B, LQ, DV]

    __nv_bfloat16 *qh, *ql, *wth, *wtl, *Qh, *Ql, *kh, *kl, *Ahp, *Alp, *vth, *vtl;
    float* sbuf;
    cudaGetSymbolAddress((void**)&qh,  g_qh);
    cudaGetSymbolAddress((void**)&ql,  g_ql);
    cudaGetSymbolAddress((void**)&wth, g_wth);
    cudaGetSymbolAddress((void**)&wtl, g_wtl);
    cudaGetSymbolAddress((void**)&Qh,  g_Qh);
    cudaGetSymbolAddress((void**)&Ql,  g_Ql);
    cudaGetSymbolAddress((void**)&kh,  g_kh);
    cudaGetSymbolAddress((void**)&kl,  g_kl);
    cudaGetSymbolAddress((void**)&sbuf, g_S);
    cudaGetSymbolAddress((void**)&Ahp, g_Ah);
    cudaGetSymbolAddress((void**)&Alp, g_Al);
    cudaGetSymbolAddress((void**)&vth, g_vth);
    cudaGetSymbolAddress((void**)&vtl, g_vtl);

    // 1) splits / transposes of inputs
    {
        size_t n4 = (size_t)BATCH * LQ * DQ / 4;
        convert_split<<<(unsigned)((n4 + 255) / 256), 256>>>(queries, qh, ql, n4);
    }
    {
        size_t n4 = (size_t)BATCH * LK * DKEY / 4;
        convert_split<<<(unsigned)((n4 + 255) / 256), 256>>>(keys, kh, kl, n4);
    }
    {
        dim3 g(DKEY / 32, DQ / 32, 1);
        transpose_split<<<g, dim3(32, 8)>>>(W_q, wth, wtl, DQ, DKEY, 0, 0);
    }
    {
        dim3 g(DV / 32, LK / 32, BATCH);
        transpose_split<<<g, dim3(32, 8)>>>(values, vth, vtl, LK, DV,
                                            (size_t)LK * DV, (size_t)DV * LK);
    }

    // 2) Q = queries @ W_q  (M = B*LQ flat, N = DKEY, K = DQ) -> split bf16
    {
        dim3 g(DKEY / 128, (BATCH * LQ) / 128, 1);
        hmma_gemm<1><<<g, 256>>>(
            qh, ql, wth, wtl, nullptr, Qh, Ql,
            DKEY, DQ, 0, 0, 0, 1.0f);
    }

    // 3) S = Q @ K^T / 32  (batched; M = LQ, N = LK, K = DKEY) -> fp32
    {
        dim3 g(LK / 128, LQ / 128, BATCH);
        hmma_gemm<0><<<g, 256>>>(
            Qh, Ql, kh, kl, sbuf, nullptr, nullptr,
            LK, DKEY,
            (size_t)LQ * DKEY, (size_t)LK * DKEY, (size_t)LQ * LK,
            0.03125f);
    }

    // 4) masked softmax -> split bf16 A
    softmax_rows_split<<<BATCH * LQ, 256>>>(sbuf, vlens, Ahp, Alp);

    // 5) out = A @ V  (batched; M = LQ, N = DV, K = LK; B operand = V^T)
    {
        dim3 g(DV / 128, LQ / 128, BATCH);
        hmma_gemm<0><<<g, 256>>>(
            Ahp, Alp, vth, vtl, out, nullptr, nullptr,
            DV, LK,
            (size_t)LQ * LK, (size_t)DV * LK, (size_t)LQ * DV,
            1.0f);
    }
}